// round 10
// baseline (speedup 1.0000x reference)
#include <cuda_runtime.h>

#define NN 50000
#define NE 600000
#define DD 128
#define GG 64

#define BM 128
#define BN 128
#define BK 16

// Scratch (device globals: allocation-free per harness rules)
__device__ float g_h[NN * DD];      // lin1 output
__device__ float g_agg[NN * DD];    // scatter-add accumulator
__device__ float g_x[NN * DD];      // pre-norm activations
__device__ float g_sum[GG * DD];
__device__ float g_sumsq[GG * DD];
__device__ float g_cnt[GG];
__device__ float g_mu[GG * DD];     // mean * mean_scale
__device__ float g_scale[GG * DD];  // weight / std

__device__ __forceinline__ float silu_f(float z) {
    return z / (1.0f + __expf(-z));
}

// Explicit global-space vector reduction (no-return). The C++ float4 atomicAdd
// overload lowers to a generic-space atom.add.v4 which traps on sm_103a.
__device__ __forceinline__ void red_add_v4(float* addr, float4 v) {
    asm volatile("red.global.add.v4.f32 [%0], {%1, %2, %3, %4};"
                 :: "l"(addr), "f"(v.x), "f"(v.y), "f"(v.z), "f"(v.w)
                 : "memory");
}

__global__ void zero_kernel() {
    int idx = blockIdx.x * blockDim.x + threadIdx.x;
    int total4 = NN * DD / 4;
    if (idx < total4) reinterpret_cast<float4*>(g_agg)[idx] = make_float4(0.f, 0.f, 0.f, 0.f);
    if (idx < GG * DD) { g_sum[idx] = 0.f; g_sumsq[idx] = 0.f; }
    if (idx < GG) g_cnt[idx] = 0.f;
}

// C[m][o] = sum_k A[m][k] * W[o][k] + bias[o]  -> g_h
__global__ void gemm_node(const float* __restrict__ A, const float* __restrict__ W,
                          const float* __restrict__ bias) {
    __shared__ float As[BK][BM + 4];
    __shared__ float Bs[BK][BN + 4];
    int tid = threadIdx.x;
    int ty = tid >> 4, tx = tid & 15;
    int m0 = blockIdx.x * BM;
    int r0 = ty * 4, c0 = tx * 4;
    float acc[8][8];
#pragma unroll
    for (int i = 0; i < 8; i++)
#pragma unroll
        for (int j = 0; j < 8; j++) acc[i][j] = 0.f;

    for (int k0 = 0; k0 < DD; k0 += BK) {
#pragma unroll
        for (int l = 0; l < 2; l++) {
            int idx = tid + l * 256;
            int m = idx >> 2;
            int kq = idx & 3;
            int gm = m0 + m;
            float4 f = make_float4(0.f, 0.f, 0.f, 0.f);
            if (gm < NN) f = *reinterpret_cast<const float4*>(A + gm * DD + k0 + kq * 4);
            As[kq * 4 + 0][m] = f.x; As[kq * 4 + 1][m] = f.y;
            As[kq * 4 + 2][m] = f.z; As[kq * 4 + 3][m] = f.w;
        }
#pragma unroll
        for (int l = 0; l < 2; l++) {
            int idx = tid + l * 256;
            int o = idx >> 2;
            int kq = idx & 3;
            float4 f = *reinterpret_cast<const float4*>(W + o * DD + k0 + kq * 4);
            Bs[kq * 4 + 0][o] = f.x; Bs[kq * 4 + 1][o] = f.y;
            Bs[kq * 4 + 2][o] = f.z; Bs[kq * 4 + 3][o] = f.w;
        }
        __syncthreads();
#pragma unroll
        for (int k = 0; k < BK; k++) {
            float a[8], b[8];
#pragma unroll
            for (int i = 0; i < 4; i++) { a[i] = As[k][r0 + i]; a[i + 4] = As[k][64 + r0 + i]; }
#pragma unroll
            for (int j = 0; j < 4; j++) { b[j] = Bs[k][c0 + j]; b[j + 4] = Bs[k][64 + c0 + j]; }
#pragma unroll
            for (int i = 0; i < 8; i++)
#pragma unroll
                for (int j = 0; j < 8; j++) acc[i][j] += a[i] * b[j];
        }
        __syncthreads();
    }

#pragma unroll
    for (int i = 0; i < 8; i++) {
        int m = m0 + (i < 4 ? r0 + i : 64 + r0 + i - 4);
        if (m >= NN) continue;
#pragma unroll
        for (int jh = 0; jh < 2; jh++) {
            int c = (jh == 0 ? c0 : 64 + c0);
            float4 v;
            v.x = acc[i][jh * 4 + 0] + bias[c + 0];
            v.y = acc[i][jh * 4 + 1] + bias[c + 1];
            v.z = acc[i][jh * 4 + 2] + bias[c + 2];
            v.w = acc[i][jh * 4 + 3] + bias[c + 3];
            *reinterpret_cast<float4*>(g_h + m * DD + c) = v;
        }
    }
}

// Fused: EL = edge_attr @ we^T + be; msg = silu(h[src] + EL); red.global agg[dst]
__global__ void gemm_edge(const float* __restrict__ A, const float* __restrict__ W,
                          const float* __restrict__ bias,
                          const int* __restrict__ src,
                          const int* __restrict__ dst) {
    __shared__ float As[BK][BM + 4];
    __shared__ float Bs[BK][BN + 4];
    int tid = threadIdx.x;
    int ty = tid >> 4, tx = tid & 15;
    int m0 = blockIdx.x * BM;
    int r0 = ty * 4, c0 = tx * 4;
    float acc[8][8];
#pragma unroll
    for (int i = 0; i < 8; i++)
#pragma unroll
        for (int j = 0; j < 8; j++) acc[i][j] = 0.f;

    for (int k0 = 0; k0 < DD; k0 += BK) {
#pragma unroll
        for (int l = 0; l < 2; l++) {
            int idx = tid + l * 256;
            int m = idx >> 2;
            int kq = idx & 3;
            int gm = m0 + m;
            float4 f = make_float4(0.f, 0.f, 0.f, 0.f);
            if (gm < NE) f = *reinterpret_cast<const float4*>(A + gm * DD + k0 + kq * 4);
            As[kq * 4 + 0][m] = f.x; As[kq * 4 + 1][m] = f.y;
            As[kq * 4 + 2][m] = f.z; As[kq * 4 + 3][m] = f.w;
        }
#pragma unroll
        for (int l = 0; l < 2; l++) {
            int idx = tid + l * 256;
            int o = idx >> 2;
            int kq = idx & 3;
            float4 f = *reinterpret_cast<const float4*>(W + o * DD + k0 + kq * 4);
            Bs[kq * 4 + 0][o] = f.x; Bs[kq * 4 + 1][o] = f.y;
            Bs[kq * 4 + 2][o] = f.z; Bs[kq * 4 + 3][o] = f.w;
        }
        __syncthreads();
#pragma unroll
        for (int k = 0; k < BK; k++) {
            float a[8], b[8];
#pragma unroll
            for (int i = 0; i < 4; i++) { a[i] = As[k][r0 + i]; a[i + 4] = As[k][64 + r0 + i]; }
#pragma unroll
            for (int j = 0; j < 4; j++) { b[j] = Bs[k][c0 + j]; b[j + 4] = Bs[k][64 + c0 + j]; }
#pragma unroll
            for (int i = 0; i < 8; i++)
#pragma unroll
                for (int j = 0; j < 8; j++) acc[i][j] += a[i] * b[j];
        }
        __syncthreads();
    }

    // Epilogue: gather h[src], silu, vector-reduction scatter to agg[dst]
#pragma unroll
    for (int i = 0; i < 8; i++) {
        int e = m0 + (i < 4 ? r0 + i : 64 + r0 + i - 4);
        if (e >= NE) continue;
        int s = src[e];
        int d = dst[e];
#pragma unroll
        for (int jh = 0; jh < 2; jh++) {
            int c = (jh == 0 ? c0 : 64 + c0);
            float4 hv = *reinterpret_cast<const float4*>(g_h + s * DD + c);
            float zx = acc[i][jh * 4 + 0] + bias[c + 0] + hv.x;
            float zy = acc[i][jh * 4 + 1] + bias[c + 1] + hv.y;
            float zz = acc[i][jh * 4 + 2] + bias[c + 2] + hv.z;
            float zw = acc[i][jh * 4 + 3] + bias[c + 3] + hv.w;
            float4 msg = make_float4(silu_f(zx), silu_f(zy), silu_f(zz), silu_f(zw));
            red_add_v4(g_agg + d * DD + c, msg);
        }
    }
}

// x = silu((1+eps)*h + agg) + node_h; accumulate per-graph sum/sumsq (batch sorted)
__global__ void stats_kernel(const float* __restrict__ node_h,
                             const int* __restrict__ batch,
                             const float* __restrict__ eps_p) {
    int d = threadIdx.x;
    int n0 = blockIdx.x * 64;
    if (n0 >= NN) return;
    int nend = min(n0 + 64, NN);
    float eps1 = 1.0f + eps_p[0];
    float s = 0.f, ss = 0.f;
    int curg = batch[n0];
    int runstart = n0;
    for (int n = n0; n < nend; n++) {
        int g = batch[n];
        if (g != curg) {
            atomicAdd(&g_sum[curg * DD + d], s);
            atomicAdd(&g_sumsq[curg * DD + d], ss);
            if (d == 0) atomicAdd(&g_cnt[curg], (float)(n - runstart));
            s = 0.f; ss = 0.f; curg = g; runstart = n;
        }
        float hv = g_h[n * DD + d];
        float a = g_agg[n * DD + d];
        float conv = eps1 * hv + a;
        float x = silu_f(conv) + node_h[n * DD + d];
        g_x[n * DD + d] = x;
        s += x; ss += x * x;
    }
    atomicAdd(&g_sum[curg * DD + d], s);
    atomicAdd(&g_sumsq[curg * DD + d], ss);
    if (d == 0) atomicAdd(&g_cnt[curg], (float)(nend - runstart));
}

// Per (g,d): mu = mean*mean_scale; scale = weight * rsqrt(var + eps)
// var = E[x^2] - mean^2 * ms * (2 - ms)   (algebraic identity for out = x - mean*ms)
__global__ void finalize_kernel(const float* __restrict__ gw, const float* __restrict__ ms) {
    int idx = blockIdx.x * blockDim.x + threadIdx.x;
    if (idx >= GG * DD) return;
    int d = idx & 127;
    int g = idx >> 7;
    float cnt = fmaxf(g_cnt[g], 1.0f);
    float mean = g_sum[idx] / cnt;
    float m2 = g_sumsq[idx] / cnt;
    float m = ms[d];
    float var = m2 - mean * mean * m * (2.0f - m);
    var = fmaxf(var, 0.0f);
    g_mu[idx] = mean * m;
    g_scale[idx] = gw[d] * rsqrtf(var + 1e-5f);
}

__global__ void apply_kernel(const int* __restrict__ batch,
                             const float* __restrict__ gb,
                             float* __restrict__ out) {
    int idx = blockIdx.x * blockDim.x + threadIdx.x;  // over NN*32 float4s
    if (idx >= NN * 32) return;
    int n = idx >> 5;
    int d4 = idx & 31;
    int g = batch[n];
    float4 x = reinterpret_cast<const float4*>(g_x)[idx];
    float4 mu = *reinterpret_cast<const float4*>(g_mu + g * DD + d4 * 4);
    float4 sc = *reinterpret_cast<const float4*>(g_scale + g * DD + d4 * 4);
    float4 b = *reinterpret_cast<const float4*>(gb + d4 * 4);
    float4 r;
    r.x = (x.x - mu.x) * sc.x + b.x;
    r.y = (x.y - mu.y) * sc.y + b.y;
    r.z = (x.z - mu.z) * sc.z + b.z;
    r.w = (x.w - mu.w) * sc.w + b.w;
    reinterpret_cast<float4*>(out)[idx] = r;
}

extern "C" void kernel_launch(void* const* d_in, const int* in_sizes, int n_in,
                              void* d_out, int out_size) {
    const float* node_h = (const float*)d_in[0];
    const float* edge_attr = (const float*)d_in[1];
    const int* batch = (const int*)d_in[2];
    const int* ei = (const int*)d_in[3];
    const float* w1 = (const float*)d_in[4];
    const float* b1 = (const float*)d_in[5];
    const float* we = (const float*)d_in[6];
    const float* be = (const float*)d_in[7];
    const float* eps = (const float*)d_in[8];
    const float* gnw = (const float*)d_in[9];
    const float* gnb = (const float*)d_in[10];
    const float* gnms = (const float*)d_in[11];
    float* out = (float*)d_out;

    zero_kernel<<<(NN * DD / 4 + 255) / 256, 256>>>();
    gemm_node<<<(NN + BM - 1) / BM, 256>>>(node_h, w1, b1);
    gemm_edge<<<(NE + BM - 1) / BM, 256>>>(edge_attr, we, be, ei, ei + NE);
    stats_kernel<<<(NN + 63) / 64, 128>>>(node_h, batch, eps);
    finalize_kernel<<<(GG * DD + 255) / 256, 256>>>(gnw, gnms);
    apply_kernel<<<(NN * 32 + 255) / 256, 256>>>(batch, gnb, out);
}

// round 13
// speedup vs baseline: 1.3856x; 1.3856x over previous
#include <cuda_runtime.h>
#include <cstdint>

#define NN 50000
#define NE 600000
#define DD 128
#define GG 64

// ---------------- scratch (device globals; allocation-free) ----------------
__device__ float g_h[NN * DD];
__device__ float g_agg[NN * DD];
__device__ float g_x[NN * DD];
__device__ float g_sum[GG * DD];
__device__ float g_sumsq[GG * DD];
__device__ float g_cnt[GG];
__device__ float g_mu[GG * DD];
__device__ float g_scale[GG * DD];

__device__ __forceinline__ float silu_f(float z) {
    return z / (1.0f + __expf(-z));
}

__device__ __forceinline__ void red_add_v4(float* addr, float4 v) {
    asm volatile("red.global.add.v4.f32 [%0], {%1, %2, %3, %4};"
                 :: "l"(addr), "f"(v.x), "f"(v.y), "f"(v.z), "f"(v.w)
                 : "memory");
}

__device__ __forceinline__ uint32_t f2tf32(float f) {
    uint32_t r;
    asm("cvt.rna.tf32.f32 %0, %1;" : "=r"(r) : "f"(f));
    return r;
}

// D (16x8) += A (16x8 k) * B (8k x 8n); tf32 inputs, f32 accum.
__device__ __forceinline__ void mma_tf32(float* c, const uint32_t* a,
                                         uint32_t b0, uint32_t b1) {
    asm volatile(
        "mma.sync.aligned.m16n8k8.row.col.f32.tf32.tf32.f32 "
        "{%0,%1,%2,%3}, {%4,%5,%6,%7}, {%8,%9}, {%0,%1,%2,%3};"
        : "+f"(c[0]), "+f"(c[1]), "+f"(c[2]), "+f"(c[3])
        : "r"(a[0]), "r"(a[1]), "r"(a[2]), "r"(a[3]), "r"(b0), "r"(b1));
}

// ---------------- tiled tensor-core GEMM (mma.sync tf32) ----------------
// smem: bias[128] f32 | W 128x132 tf32 | A-chunk 128x68 tf32  (~101 KB, occ 2)
#define WS_STRIDE 132
#define AS_STRIDE 68
#define OFF_BIAS 0
#define OFF_W    512
#define OFF_A    (512 + 128 * WS_STRIDE * 4)
#define SMEM_SZ  (OFF_A + 128 * AS_STRIDE * 4)

// EDGE=true : A=edge_attr, epi = silu(D+bias+g_h[src]) -> red.v4 g_agg[dst]
// EDGE=false: A=node_h,    epi = D+bias -> g_h
template <bool EDGE>
__global__ __launch_bounds__(256, 2)
void mma_gemm(const float* __restrict__ A, const float* __restrict__ W,
              const float* __restrict__ bias,
              const int* __restrict__ src, const int* __restrict__ dst,
              int nrows) {
    extern __shared__ char smem[];
    float* sbias = reinterpret_cast<float*>(smem + OFF_BIAS);
    uint32_t* Ws = reinterpret_cast<uint32_t*>(smem + OFF_W);
    uint32_t* As = reinterpret_cast<uint32_t*>(smem + OFF_A);

    int tid = threadIdx.x;
    int wid = tid >> 5, lid = tid & 31;
    int grp = lid >> 2, tig = lid & 3;
    int wm = wid & 3, wn = wid >> 2;

    if (tid < 128) sbias[tid] = bias[tid];
    // W tile: 128x128, stride 132, tf32-converted
#pragma unroll
    for (int i = 0; i < 16; i++) {
        int f = tid + i * 256;
        int row = f >> 5, c4 = (f & 31) * 4;
        float4 v = *reinterpret_cast<const float4*>(W + row * DD + c4);
        uint32_t* p = Ws + row * WS_STRIDE + c4;
        p[0] = f2tf32(v.x); p[1] = f2tf32(v.y);
        p[2] = f2tf32(v.z); p[3] = f2tf32(v.w);
    }

    int row0 = blockIdx.x * 128;
    float acc[2][8][4];
#pragma unroll
    for (int mf = 0; mf < 2; mf++)
#pragma unroll
        for (int nf = 0; nf < 8; nf++)
#pragma unroll
            for (int j = 0; j < 4; j++) acc[mf][nf][j] = 0.f;

#pragma unroll
    for (int kc = 0; kc < 2; kc++) {
        __syncthreads();  // kc=0: nothing pending; kc=1: all warps done with As
        // A chunk: rows row0..row0+127, k = kc*64..+63
#pragma unroll
        for (int i = 0; i < 8; i++) {
            int f = tid + i * 256;
            int row = f >> 4, c4 = (f & 15) * 4;
            int gr = row0 + row;
            float4 v = make_float4(0.f, 0.f, 0.f, 0.f);
            if (gr < nrows)
                v = *reinterpret_cast<const float4*>(A + (size_t)gr * DD + kc * 64 + c4);
            uint32_t* p = As + row * AS_STRIDE + c4;
            p[0] = f2tf32(v.x); p[1] = f2tf32(v.y);
            p[2] = f2tf32(v.z); p[3] = f2tf32(v.w);
        }
        __syncthreads();  // A chunk (and W on first pass) visible

#pragma unroll
        for (int ks = 0; ks < 8; ks++) {
            int k0 = ks * 8;
            uint32_t a[2][4];
#pragma unroll
            for (int mf = 0; mf < 2; mf++) {
                int r = wm * 32 + mf * 16 + grp;
                a[mf][0] = As[r * AS_STRIDE + k0 + tig];
                a[mf][1] = As[(r + 8) * AS_STRIDE + k0 + tig];
                a[mf][2] = As[r * AS_STRIDE + k0 + tig + 4];
                a[mf][3] = As[(r + 8) * AS_STRIDE + k0 + tig + 4];
            }
#pragma unroll
            for (int nf = 0; nf < 8; nf++) {
                int n = wn * 64 + nf * 8 + grp;
                uint32_t b0 = Ws[n * WS_STRIDE + kc * 64 + k0 + tig];
                uint32_t b1 = Ws[n * WS_STRIDE + kc * 64 + k0 + tig + 4];
                mma_tf32(acc[0][nf], a[0], b0, b1);
                mma_tf32(acc[1][nf], a[1], b0, b1);
            }
        }
    }

    // Epilogue. C frag mapping (m16n8k8): rows grp / grp+8; cols 2*tig, 2*tig+1.
    // shfl-pack lanes (tig, tig+1) -> even-tig lanes own 4 contiguous cols.
#pragma unroll
    for (int mf = 0; mf < 2; mf++) {
#pragma unroll
        for (int half = 0; half < 2; half++) {
            int r = row0 + wm * 32 + mf * 16 + grp + half * 8;
            bool rowok = (r < nrows);
            int s = 0, d = 0;
            if (EDGE && rowok) { s = src[r]; d = dst[r]; }
#pragma unroll
            for (int nf = 0; nf < 8; nf++) {
                float x0 = acc[mf][nf][half * 2];
                float x1 = acc[mf][nf][half * 2 + 1];
                float x2 = __shfl_down_sync(0xffffffffu, x0, 1);
                float x3 = __shfl_down_sync(0xffffffffu, x1, 1);
                if ((tig & 1) == 0 && rowok) {
                    int c = wn * 64 + nf * 8 + 2 * tig;  // tig 0 -> +0, tig 2 -> +4
                    float4 bv = *reinterpret_cast<const float4*>(sbias + c);
                    if (EDGE) {
                        float4 hv = *reinterpret_cast<const float4*>(g_h + (size_t)s * DD + c);
                        float4 m = make_float4(silu_f(x0 + bv.x + hv.x),
                                               silu_f(x1 + bv.y + hv.y),
                                               silu_f(x2 + bv.z + hv.z),
                                               silu_f(x3 + bv.w + hv.w));
                        red_add_v4(g_agg + (size_t)d * DD + c, m);
                    } else {
                        float4 v = make_float4(x0 + bv.x, x1 + bv.y,
                                               x2 + bv.z, x3 + bv.w);
                        *reinterpret_cast<float4*>(g_h + (size_t)r * DD + c) = v;
                    }
                }
            }
        }
    }
}

// ---------------- elementwise / norm kernels ----------------
__global__ void zero_kernel() {
    int idx = blockIdx.x * blockDim.x + threadIdx.x;
    int total4 = NN * DD / 4;
    if (idx < total4) reinterpret_cast<float4*>(g_agg)[idx] = make_float4(0.f, 0.f, 0.f, 0.f);
    if (idx < GG * DD) { g_sum[idx] = 0.f; g_sumsq[idx] = 0.f; }
    if (idx < GG) g_cnt[idx] = 0.f;
}

__device__ __forceinline__ float stats_compute(int n, int d, float eps1,
                                               const float* __restrict__ node_h) {
    float hv = g_h[n * DD + d];
    float av = g_agg[n * DD + d];
    float x = silu_f(eps1 * hv + av) + node_h[n * DD + d];
    g_x[n * DD + d] = x;
    return x;
}

// 512 threads: (q in 0..3) x (d in 0..127); 64 nodes per block.
__global__ void stats2_kernel(const float* __restrict__ node_h,
                              const int* __restrict__ batch,
                              const float* __restrict__ eps_p) {
    __shared__ float ssum[4][DD];
    __shared__ float ssq[4][DD];
    int tid = threadIdx.x;
    int d = tid & 127, q = tid >> 7;
    int n0 = blockIdx.x * 64;
    if (n0 >= NN) return;
    int nend = min(n0 + 64, NN);
    float eps1 = 1.0f + eps_p[0];
    int g0 = batch[n0], g1 = batch[nend - 1];
    int a = n0 + q * 16;
    int b = min(a + 16, nend);

    if (g0 == g1) {
        float s = 0.f, ss = 0.f;
        for (int n = a; n < b; n++) {
            float x = stats_compute(n, d, eps1, node_h);
            s += x; ss += x * x;
        }
        ssum[q][d] = s; ssq[q][d] = ss;
        __syncthreads();
        if (q == 0) {
            float S = ssum[0][d] + ssum[1][d] + ssum[2][d] + ssum[3][d];
            float Q = ssq[0][d] + ssq[1][d] + ssq[2][d] + ssq[3][d];
            atomicAdd(&g_sum[g0 * DD + d], S);
            atomicAdd(&g_sumsq[g0 * DD + d], Q);
            if (d == 0) atomicAdd(&g_cnt[g0], (float)(nend - n0));
        }
    } else {
        float s = 0.f, ss = 0.f;
        int cg = (a < b) ? batch[a] : -1;
        int rs = a;
        for (int n = a; n < b; n++) {
            int g = batch[n];
            if (g != cg) {
                atomicAdd(&g_sum[cg * DD + d], s);
                atomicAdd(&g_sumsq[cg * DD + d], ss);
                if (d == 0) atomicAdd(&g_cnt[cg], (float)(n - rs));
                s = 0.f; ss = 0.f; cg = g; rs = n;
            }
            float x = stats_compute(n, d, eps1, node_h);
            s += x; ss += x * x;
        }
        if (a < b) {
            atomicAdd(&g_sum[cg * DD + d], s);
            atomicAdd(&g_sumsq[cg * DD + d], ss);
            if (d == 0) atomicAdd(&g_cnt[cg], (float)(b - rs));
        }
    }
}

__global__ void finalize_kernel(const float* __restrict__ gw, const float* __restrict__ ms) {
    int idx = blockIdx.x * blockDim.x + threadIdx.x;
    if (idx >= GG * DD) return;
    int d = idx & 127;
    float cnt = fmaxf(g_cnt[idx >> 7], 1.0f);
    float mean = g_sum[idx] / cnt;
    float m2 = g_sumsq[idx] / cnt;
    float m = ms[d];
    float var = m2 - mean * mean * m * (2.0f - m);
    var = fmaxf(var, 0.0f);
    g_mu[idx] = mean * m;
    g_scale[idx] = gw[d] * rsqrtf(var + 1e-5f);
}

__global__ void apply_kernel(const int* __restrict__ batch,
                             const float* __restrict__ gb,
                             float* __restrict__ out) {
    int idx = blockIdx.x * blockDim.x + threadIdx.x;
    if (idx >= NN * 32) return;
    int n = idx >> 5;
    int d4 = idx & 31;
    int g = batch[n];
    float4 x = reinterpret_cast<const float4*>(g_x)[idx];
    float4 mu = *reinterpret_cast<const float4*>(g_mu + g * DD + d4 * 4);
    float4 sc = *reinterpret_cast<const float4*>(g_scale + g * DD + d4 * 4);
    float4 b = *reinterpret_cast<const float4*>(gb + d4 * 4);
    float4 r;
    r.x = (x.x - mu.x) * sc.x + b.x;
    r.y = (x.y - mu.y) * sc.y + b.y;
    r.z = (x.z - mu.z) * sc.z + b.z;
    r.w = (x.w - mu.w) * sc.w + b.w;
    reinterpret_cast<float4*>(out)[idx] = r;
}

// ---------------- launch ----------------
extern "C" void kernel_launch(void* const* d_in, const int* in_sizes, int n_in,
                              void* d_out, int out_size) {
    const float* node_h = (const float*)d_in[0];
    const float* edge_attr = (const float*)d_in[1];
    const int* batch = (const int*)d_in[2];
    const int* ei = (const int*)d_in[3];
    const float* w1 = (const float*)d_in[4];
    const float* b1 = (const float*)d_in[5];
    const float* we = (const float*)d_in[6];
    const float* be = (const float*)d_in[7];
    const float* eps = (const float*)d_in[8];
    const float* gnw = (const float*)d_in[9];
    const float* gnb = (const float*)d_in[10];
    const float* gnms = (const float*)d_in[11];
    float* out = (float*)d_out;

    cudaFuncSetAttribute(mma_gemm<false>, cudaFuncAttributeMaxDynamicSharedMemorySize, SMEM_SZ);
    cudaFuncSetAttribute(mma_gemm<true>, cudaFuncAttributeMaxDynamicSharedMemorySize, SMEM_SZ);

    const int NT_NODE = (NN + 127) / 128;   // 391
    const int NT_EDGE = (NE + 127) / 128;   // 4688

    zero_kernel<<<(NN * DD / 4 + 255) / 256, 256>>>();
    mma_gemm<false><<<NT_NODE, 256, SMEM_SZ>>>(node_h, w1, b1, nullptr, nullptr, NN);
    mma_gemm<true><<<NT_EDGE, 256, SMEM_SZ>>>(edge_attr, we, be, ei, ei + NE, NE);
    stats2_kernel<<<(NN + 63) / 64, 512>>>(node_h, batch, eps);
    finalize_kernel<<<(GG * DD + 255) / 256, 256>>>(gnw, gnms);
    apply_kernel<<<(NN * 32 + 255) / 256, 256>>>(batch, gnb, out);
}

// round 14
// speedup vs baseline: 1.5104x; 1.0901x over previous
#include <cuda_runtime.h>
#include <cstdint>

#define NN 50000
#define NE 600000
#define DD 128
#define GG 64

// ---------------- scratch (device globals; allocation-free) ----------------
__device__ float g_h[NN * DD];
__device__ float g_agg[NN * DD];
__device__ float g_x[NN * DD];
__device__ float g_sum[GG * DD];
__device__ float g_sumsq[GG * DD];
__device__ float g_cnt[GG];
__device__ float g_mu[GG * DD];
__device__ float g_scale[GG * DD];

__device__ __forceinline__ float silu_f(float z) {
    return z / (1.0f + __expf(-z));
}

__device__ __forceinline__ void red_add_v4(float* addr, float4 v) {
    asm volatile("red.global.add.v4.f32 [%0], {%1, %2, %3, %4};"
                 :: "l"(addr), "f"(v.x), "f"(v.y), "f"(v.z), "f"(v.w)
                 : "memory");
}

__device__ __forceinline__ uint32_t f2tf32(float f) {
    uint32_t r;
    asm("cvt.rna.tf32.f32 %0, %1;" : "=r"(r) : "f"(f));
    return r;
}

// D (16x8) += A (16x8 k) * B (8k x 8n); tf32 inputs, f32 accum.
__device__ __forceinline__ void mma_tf32(float* c, const uint32_t* a,
                                         uint32_t b0, uint32_t b1) {
    asm volatile(
        "mma.sync.aligned.m16n8k8.row.col.f32.tf32.tf32.f32 "
        "{%0,%1,%2,%3}, {%4,%5,%6,%7}, {%8,%9}, {%0,%1,%2,%3};"
        : "+f"(c[0]), "+f"(c[1]), "+f"(c[2]), "+f"(c[3])
        : "r"(a[0]), "r"(a[1]), "r"(a[2]), "r"(a[3]), "r"(b0), "r"(b1));
}

// ---------------- persistent tensor-core GEMM (mma.sync tf32) ----------------
// smem: bias[128] | W 128x132 tf32 | A chunk x2 (128x36 tf32 each) ~= 102.5 KB, occ 2
#define WS_STRIDE 132
#define AS_STRIDE 36
#define OFF_BIAS 0
#define OFF_W    512
#define OFF_A0   (512 + 128 * WS_STRIDE * 4)
#define OFF_A1   (OFF_A0 + 128 * AS_STRIDE * 4)
#define SMEM_SZ  (OFF_A1 + 128 * AS_STRIDE * 4)

// Load one 128x32 A chunk (k-chunk kc of tile at row0), tf32-convert into As.
__device__ __forceinline__ void load_chunk(const float* __restrict__ A, int row0, int kc,
                                           uint32_t* As, int nrows, int tid) {
#pragma unroll
    for (int i = 0; i < 4; i++) {
        int f = tid + i * 256;
        int row = f >> 3, c4 = (f & 7) * 4;
        int gr = row0 + row;
        float4 v = make_float4(0.f, 0.f, 0.f, 0.f);
        if (gr < nrows)
            v = *reinterpret_cast<const float4*>(A + (size_t)gr * DD + kc * 32 + c4);
        uint32_t* p = As + row * AS_STRIDE + c4;
        p[0] = f2tf32(v.x); p[1] = f2tf32(v.y);
        p[2] = f2tf32(v.z); p[3] = f2tf32(v.w);
    }
}

__device__ __forceinline__ void do_chunk(const uint32_t* __restrict__ Ws,
                                         const uint32_t* __restrict__ As,
                                         int kc, float acc[2][8][4],
                                         int wm, int wn, int grp, int tig) {
#pragma unroll
    for (int ks = 0; ks < 4; ks++) {
        int k0 = ks * 8;
        uint32_t a[2][4];
#pragma unroll
        for (int mf = 0; mf < 2; mf++) {
            int r = wm * 32 + mf * 16 + grp;
            a[mf][0] = As[r * AS_STRIDE + k0 + tig];
            a[mf][1] = As[(r + 8) * AS_STRIDE + k0 + tig];
            a[mf][2] = As[r * AS_STRIDE + k0 + tig + 4];
            a[mf][3] = As[(r + 8) * AS_STRIDE + k0 + tig + 4];
        }
#pragma unroll
        for (int nf = 0; nf < 8; nf++) {
            int n = wn * 64 + nf * 8 + grp;
            uint32_t b0 = Ws[n * WS_STRIDE + kc * 32 + k0 + tig];
            uint32_t b1 = Ws[n * WS_STRIDE + kc * 32 + k0 + tig + 4];
            mma_tf32(acc[0][nf], a[0], b0, b1);
            mma_tf32(acc[1][nf], a[1], b0, b1);
        }
    }
}

// EDGE=true : A=edge_attr, epi = silu(D+bias+g_h[src]) -> red.v4 g_agg[dst]
// EDGE=false: A=node_h,    epi = D+bias -> g_h
template <bool EDGE>
__global__ __launch_bounds__(256, 2)
void mma_gemm(const float* __restrict__ A, const float* __restrict__ W,
              const float* __restrict__ bias,
              const int* __restrict__ src, const int* __restrict__ dst,
              int nrows, int ntiles) {
    extern __shared__ char smem[];
    float* sbias = reinterpret_cast<float*>(smem + OFF_BIAS);
    uint32_t* Ws = reinterpret_cast<uint32_t*>(smem + OFF_W);
    uint32_t* As0 = reinterpret_cast<uint32_t*>(smem + OFF_A0);
    uint32_t* As1 = reinterpret_cast<uint32_t*>(smem + OFF_A1);

    int tid = threadIdx.x;
    int wid = tid >> 5, lid = tid & 31;
    int grp = lid >> 2, tig = lid & 3;
    int wm = wid & 3, wn = wid >> 2;

    if (tid < 128) sbias[tid] = bias[tid];
    // W tile converted ONCE per persistent CTA
#pragma unroll
    for (int i = 0; i < 16; i++) {
        int f = tid + i * 256;
        int row = f >> 5, c4 = (f & 31) * 4;
        float4 v = *reinterpret_cast<const float4*>(W + row * DD + c4);
        uint32_t* p = Ws + row * WS_STRIDE + c4;
        p[0] = f2tf32(v.x); p[1] = f2tf32(v.y);
        p[2] = f2tf32(v.z); p[3] = f2tf32(v.w);
    }

    int t = blockIdx.x;
    if (t >= ntiles) return;
    load_chunk(A, t * 128, 0, As0, nrows, tid);
    __syncthreads();

    for (; t < ntiles; t += gridDim.x) {
        int row0 = t * 128;
        float acc[2][8][4];
#pragma unroll
        for (int mf = 0; mf < 2; mf++)
#pragma unroll
            for (int nf = 0; nf < 8; nf++)
#pragma unroll
                for (int j = 0; j < 4; j++) acc[mf][nf][j] = 0.f;

        // 4 k-chunks, double buffered: chunk c+1 (or next tile's chunk 0)
        // loads while chunk c computes. Per-chunk sync covers buffer reuse.
#pragma unroll
        for (int c = 0; c < 4; c++) {
            uint32_t* cur = (c & 1) ? As1 : As0;
            if (c < 3) {
                load_chunk(A, row0, c + 1, (c & 1) ? As0 : As1, nrows, tid);
            } else {
                int tn = t + gridDim.x;
                if (tn < ntiles) load_chunk(A, tn * 128, 0, As0, nrows, tid);
            }
            do_chunk(Ws, cur, c, acc, wm, wn, grp, tig);
            __syncthreads();
        }

        // Epilogue. C frag (m16n8k8): rows grp/grp+8; cols 2*tig, 2*tig+1.
        // shfl-pack lanes (tig, tig+1) -> even-tig lanes own 4 contiguous cols.
#pragma unroll
        for (int mf = 0; mf < 2; mf++) {
#pragma unroll
            for (int half = 0; half < 2; half++) {
                int r = row0 + wm * 32 + mf * 16 + grp + half * 8;
                bool rowok = (r < nrows);
                int s = 0, d = 0;
                if (EDGE && rowok) { s = src[r]; d = dst[r]; }
#pragma unroll
                for (int nf = 0; nf < 8; nf++) {
                    float x0 = acc[mf][nf][half * 2];
                    float x1 = acc[mf][nf][half * 2 + 1];
                    float x2 = __shfl_down_sync(0xffffffffu, x0, 1);
                    float x3 = __shfl_down_sync(0xffffffffu, x1, 1);
                    if ((tig & 1) == 0 && rowok) {
                        int c = wn * 64 + nf * 8 + 2 * tig;
                        float4 bv = *reinterpret_cast<const float4*>(sbias + c);
                        if (EDGE) {
                            float4 hv = *reinterpret_cast<const float4*>(
                                g_h + (size_t)s * DD + c);
                            float4 m = make_float4(silu_f(x0 + bv.x + hv.x),
                                                   silu_f(x1 + bv.y + hv.y),
                                                   silu_f(x2 + bv.z + hv.z),
                                                   silu_f(x3 + bv.w + hv.w));
                            red_add_v4(g_agg + (size_t)d * DD + c, m);
                        } else {
                            float4 v = make_float4(x0 + bv.x, x1 + bv.y,
                                                   x2 + bv.z, x3 + bv.w);
                            *reinterpret_cast<float4*>(g_h + (size_t)r * DD + c) = v;
                        }
                    }
                }
            }
        }
        // no sync needed: next iteration's first compute reads As0 (synced at
        // c==3), and its first load targets As1 (last read at c==3, synced).
    }
}

// ---------------- elementwise / norm kernels ----------------
__global__ void zero_kernel() {
    int idx = blockIdx.x * blockDim.x + threadIdx.x;
    int total4 = NN * DD / 4;
    if (idx < total4) reinterpret_cast<float4*>(g_agg)[idx] = make_float4(0.f, 0.f, 0.f, 0.f);
    if (idx < GG * DD) { g_sum[idx] = 0.f; g_sumsq[idx] = 0.f; }
    if (idx < GG) g_cnt[idx] = 0.f;
}

// 256 threads: d4 = tid&31 (float4 column), q = tid>>5 (8 subsets of 8 nodes).
__global__ void stats3_kernel(const float* __restrict__ node_h,
                              const int* __restrict__ batch,
                              const float* __restrict__ eps_p) {
    __shared__ float4 ssum[8][32];
    __shared__ float4 ssq[8][32];
    int tid = threadIdx.x;
    int d4 = tid & 31, q = tid >> 5;
    int n0 = blockIdx.x * 64;
    if (n0 >= NN) return;
    int nend = min(n0 + 64, NN);
    float eps1 = 1.0f + eps_p[0];
    int g0 = batch[n0], g1 = batch[nend - 1];
    int a = n0 + q * 8;
    int b = min(a + 8, nend);

    if (g0 == g1) {
        float4 s = make_float4(0.f, 0.f, 0.f, 0.f);
        float4 ss = make_float4(0.f, 0.f, 0.f, 0.f);
        for (int n = a; n < b; n++) {
            int idx = n * 32 + d4;
            float4 hv = reinterpret_cast<const float4*>(g_h)[idx];
            float4 av = reinterpret_cast<const float4*>(g_agg)[idx];
            float4 nv = reinterpret_cast<const float4*>(node_h)[idx];
            float4 x;
            x.x = silu_f(eps1 * hv.x + av.x) + nv.x;
            x.y = silu_f(eps1 * hv.y + av.y) + nv.y;
            x.z = silu_f(eps1 * hv.z + av.z) + nv.z;
            x.w = silu_f(eps1 * hv.w + av.w) + nv.w;
            reinterpret_cast<float4*>(g_x)[idx] = x;
            s.x += x.x; s.y += x.y; s.z += x.z; s.w += x.w;
            ss.x += x.x * x.x; ss.y += x.y * x.y;
            ss.z += x.z * x.z; ss.w += x.w * x.w;
        }
        ssum[q][d4] = s; ssq[q][d4] = ss;
        __syncthreads();
        if (q == 0) {
            float4 S = ssum[0][d4], Q = ssq[0][d4];
#pragma unroll
            for (int j = 1; j < 8; j++) {
                float4 u = ssum[j][d4], v = ssq[j][d4];
                S.x += u.x; S.y += u.y; S.z += u.z; S.w += u.w;
                Q.x += v.x; Q.y += v.y; Q.z += v.z; Q.w += v.w;
            }
            red_add_v4(&g_sum[g0 * DD + d4 * 4], S);
            red_add_v4(&g_sumsq[g0 * DD + d4 * 4], Q);
            if (d4 == 0) atomicAdd(&g_cnt[g0], (float)(nend - n0));
        }
    } else {
        float4 s = make_float4(0.f, 0.f, 0.f, 0.f);
        float4 ss = make_float4(0.f, 0.f, 0.f, 0.f);
        int cg = (a < b) ? batch[a] : -1;
        int rs = a;
        for (int n = a; n < b; n++) {
            int g = batch[n];
            if (g != cg) {
                red_add_v4(&g_sum[cg * DD + d4 * 4], s);
                red_add_v4(&g_sumsq[cg * DD + d4 * 4], ss);
                if (d4 == 0) atomicAdd(&g_cnt[cg], (float)(n - rs));
                s = make_float4(0.f, 0.f, 0.f, 0.f);
                ss = make_float4(0.f, 0.f, 0.f, 0.f);
                cg = g; rs = n;
            }
            int idx = n * 32 + d4;
            float4 hv = reinterpret_cast<const float4*>(g_h)[idx];
            float4 av = reinterpret_cast<const float4*>(g_agg)[idx];
            float4 nv = reinterpret_cast<const float4*>(node_h)[idx];
            float4 x;
            x.x = silu_f(eps1 * hv.x + av.x) + nv.x;
            x.y = silu_f(eps1 * hv.y + av.y) + nv.y;
            x.z = silu_f(eps1 * hv.z + av.z) + nv.z;
            x.w = silu_f(eps1 * hv.w + av.w) + nv.w;
            reinterpret_cast<float4*>(g_x)[idx] = x;
            s.x += x.x; s.y += x.y; s.z += x.z; s.w += x.w;
            ss.x += x.x * x.x; ss.y += x.y * x.y;
            ss.z += x.z * x.z; ss.w += x.w * x.w;
        }
        if (a < b) {
            red_add_v4(&g_sum[cg * DD + d4 * 4], s);
            red_add_v4(&g_sumsq[cg * DD + d4 * 4], ss);
            if (d4 == 0) atomicAdd(&g_cnt[cg], (float)(b - rs));
        }
    }
}

__global__ void finalize_kernel(const float* __restrict__ gw, const float* __restrict__ ms) {
    int idx = blockIdx.x * blockDim.x + threadIdx.x;
    if (idx >= GG * DD) return;
    int d = idx & 127;
    float cnt = fmaxf(g_cnt[idx >> 7], 1.0f);
    float mean = g_sum[idx] / cnt;
    float m2 = g_sumsq[idx] / cnt;
    float m = ms[d];
    float var = m2 - mean * mean * m * (2.0f - m);
    var = fmaxf(var, 0.0f);
    g_mu[idx] = mean * m;
    g_scale[idx] = gw[d] * rsqrtf(var + 1e-5f);
}

__global__ void apply_kernel(const int* __restrict__ batch,
                             const float* __restrict__ gb,
                             float* __restrict__ out) {
    int idx = blockIdx.x * blockDim.x + threadIdx.x;
    if (idx >= NN * 32) return;
    int n = idx >> 5;
    int d4 = idx & 31;
    int g = batch[n];
    float4 x = reinterpret_cast<const float4*>(g_x)[idx];
    float4 mu = *reinterpret_cast<const float4*>(g_mu + g * DD + d4 * 4);
    float4 sc = *reinterpret_cast<const float4*>(g_scale + g * DD + d4 * 4);
    float4 b = *reinterpret_cast<const float4*>(gb + d4 * 4);
    float4 r;
    r.x = (x.x - mu.x) * sc.x + b.x;
    r.y = (x.y - mu.y) * sc.y + b.y;
    r.z = (x.z - mu.z) * sc.z + b.z;
    r.w = (x.w - mu.w) * sc.w + b.w;
    reinterpret_cast<float4*>(out)[idx] = r;
}

// ---------------- launch ----------------
extern "C" void kernel_launch(void* const* d_in, const int* in_sizes, int n_in,
                              void* d_out, int out_size) {
    const float* node_h = (const float*)d_in[0];
    const float* edge_attr = (const float*)d_in[1];
    const int* batch = (const int*)d_in[2];
    const int* ei = (const int*)d_in[3];
    const float* w1 = (const float*)d_in[4];
    const float* b1 = (const float*)d_in[5];
    const float* we = (const float*)d_in[6];
    const float* be = (const float*)d_in[7];
    const float* eps = (const float*)d_in[8];
    const float* gnw = (const float*)d_in[9];
    const float* gnb = (const float*)d_in[10];
    const float* gnms = (const float*)d_in[11];
    float* out = (float*)d_out;

    cudaFuncSetAttribute(mma_gemm<false>, cudaFuncAttributeMaxDynamicSharedMemorySize, SMEM_SZ);
    cudaFuncSetAttribute(mma_gemm<true>, cudaFuncAttributeMaxDynamicSharedMemorySize, SMEM_SZ);

    const int NT_NODE = (NN + 127) / 128;   // 391
    const int NT_EDGE = (NE + 127) / 128;   // 4688
    const int GRID = 304;                   // 2 per SM (152 SMs)

    zero_kernel<<<(NN * DD / 4 + 255) / 256, 256>>>();
    mma_gemm<false><<<GRID < NT_NODE ? GRID : NT_NODE, 256, SMEM_SZ>>>(
        node_h, w1, b1, nullptr, nullptr, NN, NT_NODE);
    mma_gemm<true><<<GRID, 256, SMEM_SZ>>>(edge_attr, we, be, ei, ei + NE, NE, NT_EDGE);
    stats3_kernel<<<(NN + 63) / 64, 256>>>(node_h, batch, eps);
    finalize_kernel<<<(GG * DD + 255) / 256, 256>>>(gnw, gnms);
    apply_kernel<<<(NN * 32 + 255) / 256, 256>>>(batch, gnb, out);
}

// round 15
// speedup vs baseline: 1.7032x; 1.1276x over previous
#include <cuda_runtime.h>
#include <cstdint>

#define NN 50000
#define NE 600000
#define DD 128
#define GG 64

// ---------------- scratch (device globals; allocation-free) ----------------
__device__ float g_h[NN * DD];
__device__ float g_agg[NN * DD];
__device__ float g_x[NN * DD];
__device__ float g_sum[GG * DD];
__device__ float g_sumsq[GG * DD];
__device__ float g_cnt[GG];
__device__ float g_mu[GG * DD];
__device__ float g_scale[GG * DD];

__device__ __forceinline__ float silu_f(float z) {
    return z / (1.0f + __expf(-z));
}

__device__ __forceinline__ void red_add_v4(float* addr, float4 v) {
    asm volatile("red.global.add.v4.f32 [%0], {%1, %2, %3, %4};"
                 :: "l"(addr), "f"(v.x), "f"(v.y), "f"(v.z), "f"(v.w)
                 : "memory");
}

// pack two f32 -> f16x2 (lo in low half)
__device__ __forceinline__ uint32_t pack_half2(float lo, float hi) {
    uint32_t r;
    asm("cvt.rn.f16x2.f32 %0, %1, %2;" : "=r"(r) : "f"(hi), "f"(lo));
    return r;
}

// D (16x8 f32) += A (16x16 f16) * B (16k x 8n f16)
__device__ __forceinline__ void mma_f16(float* c, const uint32_t* a,
                                        uint32_t b0, uint32_t b1) {
    asm volatile(
        "mma.sync.aligned.m16n8k16.row.col.f32.f16.f16.f32 "
        "{%0,%1,%2,%3}, {%4,%5,%6,%7}, {%8,%9}, {%0,%1,%2,%3};"
        : "+f"(c[0]), "+f"(c[1]), "+f"(c[2]), "+f"(c[3])
        : "r"(a[0]), "r"(a[1]), "r"(a[2]), "r"(a[3]), "r"(b0), "r"(b1));
}

// ---------------- persistent tensor-core GEMM (mma.sync fp16) ----------------
// halfs packed 2-per-u32 along K. Strides in u32: W 68, A 36 (4-bank row shift).
// smem: bias 512B | W 128x68 u32 (34.8KB) | A chunk x2 128x36 u32 (18.4KB each) ~72.5KB
#define WS_STRIDE 68
#define AS_STRIDE 36
#define OFF_BIAS 0
#define OFF_W    512
#define OFF_A0   (512 + 128 * WS_STRIDE * 4)
#define OFF_A1   (OFF_A0 + 128 * AS_STRIDE * 4)
#define SMEM_SZ  (OFF_A1 + 128 * AS_STRIDE * 4)

// Load one 128x64(f32) A chunk (k-chunk kc), fp16-convert into As (u32-packed).
__device__ __forceinline__ void load_chunk(const float* __restrict__ A, int row0, int kc,
                                           uint32_t* As, int nrows, int tid) {
#pragma unroll
    for (int i = 0; i < 8; i++) {
        int f = tid + i * 256;              // 0..2047
        int row = f >> 4, q = f & 15;       // 16 float4 per row-chunk
        int gr = row0 + row;
        float4 v = make_float4(0.f, 0.f, 0.f, 0.f);
        if (gr < nrows)
            v = *reinterpret_cast<const float4*>(A + (size_t)gr * DD + kc * 64 + q * 4);
        uint32_t* p = As + row * AS_STRIDE + q * 2;
        p[0] = pack_half2(v.x, v.y);
        p[1] = pack_half2(v.z, v.w);
    }
}

__device__ __forceinline__ void do_chunk(const uint32_t* __restrict__ Ws,
                                         const uint32_t* __restrict__ As,
                                         int kc, float acc[2][8][4],
                                         int wm, int wn, int grp, int tig) {
#pragma unroll
    for (int ks = 0; ks < 4; ks++) {
        int k0 = ks * 8;                    // u32 offset within chunk (16 halfs)
        uint32_t a[2][4];
#pragma unroll
        for (int mf = 0; mf < 2; mf++) {
            int r = wm * 32 + mf * 16 + grp;
            a[mf][0] = As[r * AS_STRIDE + k0 + tig];
            a[mf][1] = As[(r + 8) * AS_STRIDE + k0 + tig];
            a[mf][2] = As[r * AS_STRIDE + k0 + tig + 4];
            a[mf][3] = As[(r + 8) * AS_STRIDE + k0 + tig + 4];
        }
#pragma unroll
        for (int nf = 0; nf < 8; nf++) {
            int n = wn * 64 + nf * 8 + grp;
            uint32_t b0 = Ws[n * WS_STRIDE + kc * 32 + k0 + tig];
            uint32_t b1 = Ws[n * WS_STRIDE + kc * 32 + k0 + tig + 4];
            mma_f16(acc[0][nf], a[0], b0, b1);
            mma_f16(acc[1][nf], a[1], b0, b1);
        }
    }
}

// EDGE=true : A=edge_attr, epi = silu(D+bias+g_h[src]) -> red.v4 g_agg[dst]
// EDGE=false: A=node_h,    epi = D+bias -> g_h
template <bool EDGE>
__global__ __launch_bounds__(256, 2)
void mma_gemm(const float* __restrict__ A, const float* __restrict__ W,
              const float* __restrict__ bias,
              const int* __restrict__ src, const int* __restrict__ dst,
              int nrows, int ntiles) {
    extern __shared__ char smem[];
    float* sbias = reinterpret_cast<float*>(smem + OFF_BIAS);
    uint32_t* Ws = reinterpret_cast<uint32_t*>(smem + OFF_W);
    uint32_t* As0 = reinterpret_cast<uint32_t*>(smem + OFF_A0);
    uint32_t* As1 = reinterpret_cast<uint32_t*>(smem + OFF_A1);

    int tid = threadIdx.x;
    int wid = tid >> 5, lid = tid & 31;
    int grp = lid >> 2, tig = lid & 3;
    int wm = wid & 3, wn = wid >> 2;

    if (tid < 128) sbias[tid] = bias[tid];
    // W tile converted ONCE per persistent CTA (128x128 f32 -> f16x2)
#pragma unroll
    for (int i = 0; i < 16; i++) {
        int f = tid + i * 256;
        int row = f >> 5, q = f & 31;
        float4 v = *reinterpret_cast<const float4*>(W + row * DD + q * 4);
        uint32_t* p = Ws + row * WS_STRIDE + q * 2;
        p[0] = pack_half2(v.x, v.y);
        p[1] = pack_half2(v.z, v.w);
    }

    int t = blockIdx.x;
    if (t >= ntiles) return;
    load_chunk(A, t * 128, 0, As0, nrows, tid);
    __syncthreads();

    for (; t < ntiles; t += gridDim.x) {
        int row0 = t * 128;
        float acc[2][8][4];
#pragma unroll
        for (int mf = 0; mf < 2; mf++)
#pragma unroll
            for (int nf = 0; nf < 8; nf++)
#pragma unroll
                for (int j = 0; j < 4; j++) acc[mf][nf][j] = 0.f;

        // 2 k-chunks (64 f32 each), double buffered.
#pragma unroll
        for (int c = 0; c < 2; c++) {
            uint32_t* cur = (c & 1) ? As1 : As0;
            if (c == 0) {
                load_chunk(A, row0, 1, As1, nrows, tid);
            } else {
                int tn = t + gridDim.x;
                if (tn < ntiles) load_chunk(A, tn * 128, 0, As0, nrows, tid);
            }
            do_chunk(Ws, cur, c, acc, wm, wn, grp, tig);
            __syncthreads();
        }

        // Epilogue. C frag: rows grp/grp+8; cols 2*tig, 2*tig+1.
        // shfl-pack lanes (tig, tig+1) -> even-tig lanes own 4 contiguous cols.
#pragma unroll
        for (int mf = 0; mf < 2; mf++) {
#pragma unroll
            for (int half = 0; half < 2; half++) {
                int r = row0 + wm * 32 + mf * 16 + grp + half * 8;
                bool rowok = (r < nrows);
                int s = 0, d = 0;
                if (EDGE && rowok) { s = src[r]; d = dst[r]; }
#pragma unroll
                for (int nf = 0; nf < 8; nf++) {
                    float x0 = acc[mf][nf][half * 2];
                    float x1 = acc[mf][nf][half * 2 + 1];
                    float x2 = __shfl_down_sync(0xffffffffu, x0, 1);
                    float x3 = __shfl_down_sync(0xffffffffu, x1, 1);
                    if ((tig & 1) == 0 && rowok) {
                        int c = wn * 64 + nf * 8 + 2 * tig;
                        float4 bv = *reinterpret_cast<const float4*>(sbias + c);
                        if (EDGE) {
                            float4 hv = *reinterpret_cast<const float4*>(
                                g_h + (size_t)s * DD + c);
                            float4 m = make_float4(silu_f(x0 + bv.x + hv.x),
                                                   silu_f(x1 + bv.y + hv.y),
                                                   silu_f(x2 + bv.z + hv.z),
                                                   silu_f(x3 + bv.w + hv.w));
                            red_add_v4(g_agg + (size_t)d * DD + c, m);
                        } else {
                            float4 v = make_float4(x0 + bv.x, x1 + bv.y,
                                                   x2 + bv.z, x3 + bv.w);
                            *reinterpret_cast<float4*>(g_h + (size_t)r * DD + c) = v;
                        }
                    }
                }
            }
        }
        // no sync needed: next iter's first compute reads As0 (synced at c==1),
        // and its first load targets As1 (last read before that same sync).
    }
}

// ---------------- elementwise / norm kernels ----------------
__global__ void zero_kernel() {
    int idx = blockIdx.x * blockDim.x + threadIdx.x;
    int total4 = NN * DD / 4;
    if (idx < total4) reinterpret_cast<float4*>(g_agg)[idx] = make_float4(0.f, 0.f, 0.f, 0.f);
    if (idx < GG * DD) { g_sum[idx] = 0.f; g_sumsq[idx] = 0.f; }
    if (idx < GG) g_cnt[idx] = 0.f;
}

// 256 threads: d4 = tid&31 (float4 column), q = tid>>5 (8 subsets of 8 nodes).
__global__ void stats3_kernel(const float* __restrict__ node_h,
                              const int* __restrict__ batch,
                              const float* __restrict__ eps_p) {
    __shared__ float4 ssum[8][32];
    __shared__ float4 ssq[8][32];
    int tid = threadIdx.x;
    int d4 = tid & 31, q = tid >> 5;
    int n0 = blockIdx.x * 64;
    if (n0 >= NN) return;
    int nend = min(n0 + 64, NN);
    float eps1 = 1.0f + eps_p[0];
    int g0 = batch[n0], g1 = batch[nend - 1];
    int a = n0 + q * 8;
    int b = min(a + 8, nend);

    if (g0 == g1) {
        float4 s = make_float4(0.f, 0.f, 0.f, 0.f);
        float4 ss = make_float4(0.f, 0.f, 0.f, 0.f);
        for (int n = a; n < b; n++) {
            int idx = n * 32 + d4;
            float4 hv = reinterpret_cast<const float4*>(g_h)[idx];
            float4 av = reinterpret_cast<const float4*>(g_agg)[idx];
            float4 nv = reinterpret_cast<const float4*>(node_h)[idx];
            float4 x;
            x.x = silu_f(eps1 * hv.x + av.x) + nv.x;
            x.y = silu_f(eps1 * hv.y + av.y) + nv.y;
            x.z = silu_f(eps1 * hv.z + av.z) + nv.z;
            x.w = silu_f(eps1 * hv.w + av.w) + nv.w;
            reinterpret_cast<float4*>(g_x)[idx] = x;
            s.x += x.x; s.y += x.y; s.z += x.z; s.w += x.w;
            ss.x += x.x * x.x; ss.y += x.y * x.y;
            ss.z += x.z * x.z; ss.w += x.w * x.w;
        }
        ssum[q][d4] = s; ssq[q][d4] = ss;
        __syncthreads();
        if (q == 0) {
            float4 S = ssum[0][d4], Q = ssq[0][d4];
#pragma unroll
            for (int j = 1; j < 8; j++) {
                float4 u = ssum[j][d4], v = ssq[j][d4];
                S.x += u.x; S.y += u.y; S.z += u.z; S.w += u.w;
                Q.x += v.x; Q.y += v.y; Q.z += v.z; Q.w += v.w;
            }
            red_add_v4(&g_sum[g0 * DD + d4 * 4], S);
            red_add_v4(&g_sumsq[g0 * DD + d4 * 4], Q);
            if (d4 == 0) atomicAdd(&g_cnt[g0], (float)(nend - n0));
        }
    } else {
        float4 s = make_float4(0.f, 0.f, 0.f, 0.f);
        float4 ss = make_float4(0.f, 0.f, 0.f, 0.f);
        int cg = (a < b) ? batch[a] : -1;
        int rs = a;
        for (int n = a; n < b; n++) {
            int g = batch[n];
            if (g != cg) {
                red_add_v4(&g_sum[cg * DD + d4 * 4], s);
                red_add_v4(&g_sumsq[cg * DD + d4 * 4], ss);
                if (d4 == 0) atomicAdd(&g_cnt[cg], (float)(n - rs));
                s = make_float4(0.f, 0.f, 0.f, 0.f);
                ss = make_float4(0.f, 0.f, 0.f, 0.f);
                cg = g; rs = n;
            }
            int idx = n * 32 + d4;
            float4 hv = reinterpret_cast<const float4*>(g_h)[idx];
            float4 av = reinterpret_cast<const float4*>(g_agg)[idx];
            float4 nv = reinterpret_cast<const float4*>(node_h)[idx];
            float4 x;
            x.x = silu_f(eps1 * hv.x + av.x) + nv.x;
            x.y = silu_f(eps1 * hv.y + av.y) + nv.y;
            x.z = silu_f(eps1 * hv.z + av.z) + nv.z;
            x.w = silu_f(eps1 * hv.w + av.w) + nv.w;
            reinterpret_cast<float4*>(g_x)[idx] = x;
            s.x += x.x; s.y += x.y; s.z += x.z; s.w += x.w;
            ss.x += x.x * x.x; ss.y += x.y * x.y;
            ss.z += x.z * x.z; ss.w += x.w * x.w;
        }
        if (a < b) {
            red_add_v4(&g_sum[cg * DD + d4 * 4], s);
            red_add_v4(&g_sumsq[cg * DD + d4 * 4], ss);
            if (d4 == 0) atomicAdd(&g_cnt[cg], (float)(b - rs));
        }
    }
}

__global__ void finalize_kernel(const float* __restrict__ gw, const float* __restrict__ ms) {
    int idx = blockIdx.x * blockDim.x + threadIdx.x;
    if (idx >= GG * DD) return;
    int d = idx & 127;
    float cnt = fmaxf(g_cnt[idx >> 7], 1.0f);
    float mean = g_sum[idx] / cnt;
    float m2 = g_sumsq[idx] / cnt;
    float m = ms[d];
    float var = m2 - mean * mean * m * (2.0f - m);
    var = fmaxf(var, 0.0f);
    g_mu[idx] = mean * m;
    g_scale[idx] = gw[d] * rsqrtf(var + 1e-5f);
}

__global__ void apply_kernel(const int* __restrict__ batch,
                             const float* __restrict__ gb,
                             float* __restrict__ out) {
    int idx = blockIdx.x * blockDim.x + threadIdx.x;
    if (idx >= NN * 32) return;
    int n = idx >> 5;
    int d4 = idx & 31;
    int g = batch[n];
    float4 x = reinterpret_cast<const float4*>(g_x)[idx];
    float4 mu = *reinterpret_cast<const float4*>(g_mu + g * DD + d4 * 4);
    float4 sc = *reinterpret_cast<const float4*>(g_scale + g * DD + d4 * 4);
    float4 b = *reinterpret_cast<const float4*>(gb + d4 * 4);
    float4 r;
    r.x = (x.x - mu.x) * sc.x + b.x;
    r.y = (x.y - mu.y) * sc.y + b.y;
    r.z = (x.z - mu.z) * sc.z + b.z;
    r.w = (x.w - mu.w) * sc.w + b.w;
    reinterpret_cast<float4*>(out)[idx] = r;
}

// ---------------- launch ----------------
extern "C" void kernel_launch(void* const* d_in, const int* in_sizes, int n_in,
                              void* d_out, int out_size) {
    const float* node_h = (const float*)d_in[0];
    const float* edge_attr = (const float*)d_in[1];
    const int* batch = (const int*)d_in[2];
    const int* ei = (const int*)d_in[3];
    const float* w1 = (const float*)d_in[4];
    const float* b1 = (const float*)d_in[5];
    const float* we = (const float*)d_in[6];
    const float* be = (const float*)d_in[7];
    const float* eps = (const float*)d_in[8];
    const float* gnw = (const float*)d_in[9];
    const float* gnb = (const float*)d_in[10];
    const float* gnms = (const float*)d_in[11];
    float* out = (float*)d_out;

    cudaFuncSetAttribute(mma_gemm<false>, cudaFuncAttributeMaxDynamicSharedMemorySize, SMEM_SZ);
    cudaFuncSetAttribute(mma_gemm<true>, cudaFuncAttributeMaxDynamicSharedMemorySize, SMEM_SZ);

    const int NT_NODE = (NN + 127) / 128;   // 391
    const int NT_EDGE = (NE + 127) / 128;   // 4688
    const int GRID = 304;                   // 2 per SM (152 SMs)

    zero_kernel<<<(NN * DD / 4 + 255) / 256, 256>>>();
    mma_gemm<false><<<GRID < NT_NODE ? GRID : NT_NODE, 256, SMEM_SZ>>>(
        node_h, w1, b1, nullptr, nullptr, NN, NT_NODE);
    mma_gemm<true><<<GRID, 256, SMEM_SZ>>>(edge_attr, we, be, ei, ei + NE, NE, NT_EDGE);
    stats3_kernel<<<(NN + 63) / 64, 256>>>(node_h, batch, eps);
    finalize_kernel<<<(GG * DD + 255) / 256, 256>>>(gnw, gnms);
    apply_kernel<<<(NN * 32 + 255) / 256, 256>>>(batch, gnb, out);
}

// round 16
// speedup vs baseline: 1.7209x; 1.0104x over previous
#include <cuda_runtime.h>
#include <cstdint>

#define NN 50000
#define NE 600000
#define DD 128
#define GG 64

// ---------------- scratch (device globals; allocation-free) ----------------
__device__ float g_h[NN * DD];
__device__ float g_agg[NN * DD];
__device__ float g_x[NN * DD];
__device__ float g_sum[GG * DD];
__device__ float g_sumsq[GG * DD];
__device__ float g_cnt[GG];
__device__ float g_mu[GG * DD];
__device__ float g_scale[GG * DD];

__device__ __forceinline__ float silu_f(float z) {
    return z / (1.0f + __expf(-z));
}

__device__ __forceinline__ void red_add_v4(float* addr, float4 v) {
    asm volatile("red.global.add.v4.f32 [%0], {%1, %2, %3, %4};"
                 :: "l"(addr), "f"(v.x), "f"(v.y), "f"(v.z), "f"(v.w)
                 : "memory");
}

// pack two f32 -> f16x2 (lo in low half)
__device__ __forceinline__ uint32_t pack_half2(float lo, float hi) {
    uint32_t r;
    asm("cvt.rn.f16x2.f32 %0, %1, %2;" : "=r"(r) : "f"(hi), "f"(lo));
    return r;
}

__device__ __forceinline__ uint32_t smem_u32(const void* p) {
    uint32_t a;
    asm("{ .reg .u64 t; cvta.to.shared.u64 t, %1; cvt.u32.u64 %0, t; }" : "=r"(a) : "l"(p));
    return a;
}

__device__ __forceinline__ void ldmatrix_x4(uint32_t& r0, uint32_t& r1,
                                            uint32_t& r2, uint32_t& r3, uint32_t addr) {
    asm volatile("ldmatrix.sync.aligned.m8n8.x4.shared.b16 {%0,%1,%2,%3}, [%4];"
                 : "=r"(r0), "=r"(r1), "=r"(r2), "=r"(r3) : "r"(addr));
}

// D (16x8 f32) += A (16x16 f16) * B (16k x 8n f16)
__device__ __forceinline__ void mma_f16(float* c, const uint32_t* a,
                                        uint32_t b0, uint32_t b1) {
    asm volatile(
        "mma.sync.aligned.m16n8k16.row.col.f32.f16.f16.f32 "
        "{%0,%1,%2,%3}, {%4,%5,%6,%7}, {%8,%9}, {%0,%1,%2,%3};"
        : "+f"(c[0]), "+f"(c[1]), "+f"(c[2]), "+f"(c[3])
        : "r"(a[0]), "r"(a[1]), "r"(a[2]), "r"(a[3]), "r"(b0), "r"(b1));
}

// ---------------- persistent tensor-core GEMM (mma.sync fp16 + ldmatrix) ---
// halfs packed 2-per-u32 along K. Strides in u32: W 68 (272B), A 36 (144B):
// 16B shift per row -> ldmatrix 8-row fetches are bank-conflict-free.
#define WS_STRIDE 68
#define AS_STRIDE 36
#define OFF_BIAS 0
#define OFF_W    512
#define OFF_A0   (512 + 128 * WS_STRIDE * 4)
#define OFF_A1   (OFF_A0 + 128 * AS_STRIDE * 4)
#define SMEM_SZ  (OFF_A1 + 128 * AS_STRIDE * 4)

// Load one 128x64(f32) A chunk (k-chunk kc), fp16-convert into As (u32-packed).
__device__ __forceinline__ void load_chunk(const float* __restrict__ A, int row0, int kc,
                                           uint32_t* As, int nrows, int tid) {
#pragma unroll
    for (int i = 0; i < 8; i++) {
        int f = tid + i * 256;              // 0..2047
        int row = f >> 4, q = f & 15;       // 16 float4 per row-chunk
        int gr = row0 + row;
        float4 v = make_float4(0.f, 0.f, 0.f, 0.f);
        if (gr < nrows)
            v = *reinterpret_cast<const float4*>(A + (size_t)gr * DD + kc * 64 + q * 4);
        uint32_t* p = As + row * AS_STRIDE + q * 2;
        p[0] = pack_half2(v.x, v.y);
        p[1] = pack_half2(v.z, v.w);
    }
}

// ldmatrix-based mainloop chunk. Lane seg mapping (seg = lid>>3):
//   A x4: m0 row+0/k+0, m1 row+8/k+0, m2 row+0/k+4(u32), m3 row+8/k+4
//   B x4 over nf-pair: m0 n+0/k, m1 n+8/k, m2 n+0/k+4, m3 n+8/k+4
__device__ __forceinline__ void do_chunk(uint32_t WsB, uint32_t AsB,
                                         int kc, float acc[2][8][4],
                                         int wm, int wn, int lid) {
    int lrow = lid & 7, seg = lid >> 3;
    int rsel = (seg & 1) * 8, ksel = (seg >> 1) * 4;
    uint32_t a_base = AsB + (uint32_t)(((wm * 32 + rsel + lrow) * AS_STRIDE + ksel) * 4);
    uint32_t b_base = WsB + (uint32_t)(((wn * 64 + rsel + lrow) * WS_STRIDE
                                        + kc * 32 + ksel) * 4);
#pragma unroll
    for (int ks = 0; ks < 4; ks++) {
        uint32_t a[2][4];
        ldmatrix_x4(a[0][0], a[0][1], a[0][2], a[0][3], a_base + ks * 32);
        ldmatrix_x4(a[1][0], a[1][1], a[1][2], a[1][3],
                    a_base + 16 * AS_STRIDE * 4 + ks * 32);
#pragma unroll
        for (int nfp = 0; nfp < 4; nfp++) {
            uint32_t b00, b01, b10, b11;
            ldmatrix_x4(b00, b01, b10, b11,
                        b_base + nfp * 16 * WS_STRIDE * 4 + ks * 32);
            mma_f16(acc[0][nfp * 2],     a[0], b00, b10);
            mma_f16(acc[1][nfp * 2],     a[1], b00, b10);
            mma_f16(acc[0][nfp * 2 + 1], a[0], b01, b11);
            mma_f16(acc[1][nfp * 2 + 1], a[1], b01, b11);
        }
    }
}

// EDGE=true : A=edge_attr, epi = silu(D+bias+g_h[src]) -> red.v4 g_agg[dst]
// EDGE=false: A=node_h,    epi = D+bias -> g_h
template <bool EDGE>
__global__ __launch_bounds__(256, 2)
void mma_gemm(const float* __restrict__ A, const float* __restrict__ W,
              const float* __restrict__ bias,
              const int* __restrict__ src, const int* __restrict__ dst,
              int nrows, int ntiles) {
    extern __shared__ char smem[];
    float* sbias = reinterpret_cast<float*>(smem + OFF_BIAS);
    uint32_t* Ws = reinterpret_cast<uint32_t*>(smem + OFF_W);
    uint32_t* As0 = reinterpret_cast<uint32_t*>(smem + OFF_A0);
    uint32_t* As1 = reinterpret_cast<uint32_t*>(smem + OFF_A1);
    uint32_t sb = smem_u32(smem);
    uint32_t WsB = sb + OFF_W, AsB0 = sb + OFF_A0, AsB1 = sb + OFF_A1;

    int tid = threadIdx.x;
    int wid = tid >> 5, lid = tid & 31;
    int grp = lid >> 2, tig = lid & 3;
    int wm = wid & 3, wn = wid >> 2;

    if (tid < 128) sbias[tid] = bias[tid];
    // W tile converted ONCE per persistent CTA (128x128 f32 -> f16x2)
#pragma unroll
    for (int i = 0; i < 16; i++) {
        int f = tid + i * 256;
        int row = f >> 5, q = f & 31;
        float4 v = *reinterpret_cast<const float4*>(W + row * DD + q * 4);
        uint32_t* p = Ws + row * WS_STRIDE + q * 2;
        p[0] = pack_half2(v.x, v.y);
        p[1] = pack_half2(v.z, v.w);
    }

    int t = blockIdx.x;
    if (t >= ntiles) return;
    load_chunk(A, t * 128, 0, As0, nrows, tid);
    __syncthreads();

    for (; t < ntiles; t += gridDim.x) {
        int row0 = t * 128;
        float acc[2][8][4];
#pragma unroll
        for (int mf = 0; mf < 2; mf++)
#pragma unroll
            for (int nf = 0; nf < 8; nf++)
#pragma unroll
                for (int j = 0; j < 4; j++) acc[mf][nf][j] = 0.f;

        // 2 k-chunks (64 f32 each), double buffered.
#pragma unroll
        for (int c = 0; c < 2; c++) {
            uint32_t curB = (c & 1) ? AsB1 : AsB0;
            if (c == 0) {
                load_chunk(A, row0, 1, As1, nrows, tid);
            } else {
                int tn = t + gridDim.x;
                if (tn < ntiles) load_chunk(A, tn * 128, 0, As0, nrows, tid);
            }
            do_chunk(WsB, curB, c, acc, wm, wn, lid);
            __syncthreads();
        }

        // Epilogue. C frag: rows grp/grp+8; cols 2*tig, 2*tig+1.
        // shfl-pack lanes (tig, tig+1) -> even-tig lanes own 4 contiguous cols.
#pragma unroll
        for (int mf = 0; mf < 2; mf++) {
#pragma unroll
            for (int half = 0; half < 2; half++) {
                int r = row0 + wm * 32 + mf * 16 + grp + half * 8;
                bool rowok = (r < nrows);
                int s = 0, d = 0;
                if (EDGE && rowok) { s = src[r]; d = dst[r]; }
#pragma unroll
                for (int nf = 0; nf < 8; nf++) {
                    float x0 = acc[mf][nf][half * 2];
                    float x1 = acc[mf][nf][half * 2 + 1];
                    float x2 = __shfl_down_sync(0xffffffffu, x0, 1);
                    float x3 = __shfl_down_sync(0xffffffffu, x1, 1);
                    if ((tig & 1) == 0 && rowok) {
                        int c = wn * 64 + nf * 8 + 2 * tig;
                        float4 bv = *reinterpret_cast<const float4*>(sbias + c);
                        if (EDGE) {
                            float4 hv = *reinterpret_cast<const float4*>(
                                g_h + (size_t)s * DD + c);
                            float4 m = make_float4(silu_f(x0 + bv.x + hv.x),
                                                   silu_f(x1 + bv.y + hv.y),
                                                   silu_f(x2 + bv.z + hv.z),
                                                   silu_f(x3 + bv.w + hv.w));
                            red_add_v4(g_agg + (size_t)d * DD + c, m);
                        } else {
                            float4 v = make_float4(x0 + bv.x, x1 + bv.y,
                                                   x2 + bv.z, x3 + bv.w);
                            *reinterpret_cast<float4*>(g_h + (size_t)r * DD + c) = v;
                        }
                    }
                }
            }
        }
        // no sync needed: next iter's first compute reads As0 (synced at c==1),
        // and its first load targets As1 (last read before that same sync).
    }
}

// ---------------- elementwise / norm kernels ----------------
__global__ void zero_agg_kernel() {
    int idx = blockIdx.x * blockDim.x + threadIdx.x;
    if (idx < NN * 32)
        reinterpret_cast<float4*>(g_agg)[idx] = make_float4(0.f, 0.f, 0.f, 0.f);
}

__global__ void zero_stats_kernel() {
    int idx = blockIdx.x * blockDim.x + threadIdx.x;
    if (idx < GG * DD) { g_sum[idx] = 0.f; g_sumsq[idx] = 0.f; }
    if (idx < GG) g_cnt[idx] = 0.f;
}

// 256 threads: d4 = tid&31 (float4 column), q = tid>>5 (8 subsets of 8 nodes).
__global__ void stats3_kernel(const float* __restrict__ node_h,
                              const int* __restrict__ batch,
                              const float* __restrict__ eps_p) {
    __shared__ float4 ssum[8][32];
    __shared__ float4 ssq[8][32];
    int tid = threadIdx.x;
    int d4 = tid & 31, q = tid >> 5;
    int n0 = blockIdx.x * 64;
    if (n0 >= NN) return;
    int nend = min(n0 + 64, NN);
    float eps1 = 1.0f + eps_p[0];
    int g0 = batch[n0], g1 = batch[nend - 1];
    int a = n0 + q * 8;
    int b = min(a + 8, nend);

    if (g0 == g1) {
        float4 s = make_float4(0.f, 0.f, 0.f, 0.f);
        float4 ss = make_float4(0.f, 0.f, 0.f, 0.f);
        for (int n = a; n < b; n++) {
            int idx = n * 32 + d4;
            float4 hv = reinterpret_cast<const float4*>(g_h)[idx];
            float4 av = reinterpret_cast<const float4*>(g_agg)[idx];
            float4 nv = reinterpret_cast<const float4*>(node_h)[idx];
            float4 x;
            x.x = silu_f(eps1 * hv.x + av.x) + nv.x;
            x.y = silu_f(eps1 * hv.y + av.y) + nv.y;
            x.z = silu_f(eps1 * hv.z + av.z) + nv.z;
            x.w = silu_f(eps1 * hv.w + av.w) + nv.w;
            reinterpret_cast<float4*>(g_x)[idx] = x;
            s.x += x.x; s.y += x.y; s.z += x.z; s.w += x.w;
            ss.x += x.x * x.x; ss.y += x.y * x.y;
            ss.z += x.z * x.z; ss.w += x.w * x.w;
        }
        ssum[q][d4] = s; ssq[q][d4] = ss;
        __syncthreads();
        if (q == 0) {
            float4 S = ssum[0][d4], Q = ssq[0][d4];
#pragma unroll
            for (int j = 1; j < 8; j++) {
                float4 u = ssum[j][d4], v = ssq[j][d4];
                S.x += u.x; S.y += u.y; S.z += u.z; S.w += u.w;
                Q.x += v.x; Q.y += v.y; Q.z += v.z; Q.w += v.w;
            }
            red_add_v4(&g_sum[g0 * DD + d4 * 4], S);
            red_add_v4(&g_sumsq[g0 * DD + d4 * 4], Q);
            if (d4 == 0) atomicAdd(&g_cnt[g0], (float)(nend - n0));
        }
    } else {
        float4 s = make_float4(0.f, 0.f, 0.f, 0.f);
        float4 ss = make_float4(0.f, 0.f, 0.f, 0.f);
        int cg = (a < b) ? batch[a] : -1;
        int rs = a;
        for (int n = a; n < b; n++) {
            int g = batch[n];
            if (g != cg) {
                red_add_v4(&g_sum[cg * DD + d4 * 4], s);
                red_add_v4(&g_sumsq[cg * DD + d4 * 4], ss);
                if (d4 == 0) atomicAdd(&g_cnt[cg], (float)(n - rs));
                s = make_float4(0.f, 0.f, 0.f, 0.f);
                ss = make_float4(0.f, 0.f, 0.f, 0.f);
                cg = g; rs = n;
            }
            int idx = n * 32 + d4;
            float4 hv = reinterpret_cast<const float4*>(g_h)[idx];
            float4 av = reinterpret_cast<const float4*>(g_agg)[idx];
            float4 nv = reinterpret_cast<const float4*>(node_h)[idx];
            float4 x;
            x.x = silu_f(eps1 * hv.x + av.x) + nv.x;
            x.y = silu_f(eps1 * hv.y + av.y) + nv.y;
            x.z = silu_f(eps1 * hv.z + av.z) + nv.z;
            x.w = silu_f(eps1 * hv.w + av.w) + nv.w;
            reinterpret_cast<float4*>(g_x)[idx] = x;
            s.x += x.x; s.y += x.y; s.z += x.z; s.w += x.w;
            ss.x += x.x * x.x; ss.y += x.y * x.y;
            ss.z += x.z * x.z; ss.w += x.w * x.w;
        }
        if (a < b) {
            red_add_v4(&g_sum[cg * DD + d4 * 4], s);
            red_add_v4(&g_sumsq[cg * DD + d4 * 4], ss);
            if (d4 == 0) atomicAdd(&g_cnt[cg], (float)(b - rs));
        }
    }
}

__global__ void finalize_kernel(const float* __restrict__ gw, const float* __restrict__ ms) {
    int idx = blockIdx.x * blockDim.x + threadIdx.x;
    if (idx >= GG * DD) return;
    int d = idx & 127;
    float cnt = fmaxf(g_cnt[idx >> 7], 1.0f);
    float mean = g_sum[idx] / cnt;
    float m2 = g_sumsq[idx] / cnt;
    float m = ms[d];
    float var = m2 - mean * mean * m * (2.0f - m);
    var = fmaxf(var, 0.0f);
    g_mu[idx] = mean * m;
    g_scale[idx] = gw[d] * rsqrtf(var + 1e-5f);
}

__global__ void apply_kernel(const int* __restrict__ batch,
                             const float* __restrict__ gb,
                             float* __restrict__ out) {
    int idx = blockIdx.x * blockDim.x + threadIdx.x;
    if (idx >= NN * 32) return;
    int n = idx >> 5;
    int d4 = idx & 31;
    int g = batch[n];
    float4 x = reinterpret_cast<const float4*>(g_x)[idx];
    float4 mu = *reinterpret_cast<const float4*>(g_mu + g * DD + d4 * 4);
    float4 sc = *reinterpret_cast<const float4*>(g_scale + g * DD + d4 * 4);
    float4 b = *reinterpret_cast<const float4*>(gb + d4 * 4);
    float4 r;
    r.x = (x.x - mu.x) * sc.x + b.x;
    r.y = (x.y - mu.y) * sc.y + b.y;
    r.z = (x.z - mu.z) * sc.z + b.z;
    r.w = (x.w - mu.w) * sc.w + b.w;
    reinterpret_cast<float4*>(out)[idx] = r;
}

// ---------------- launch ----------------
// Order puts the edge GEMM at launch #4 (the slot ncu has been profiling),
// so next round's profile shows the dominant kernel.
extern "C" void kernel_launch(void* const* d_in, const int* in_sizes, int n_in,
                              void* d_out, int out_size) {
    const float* node_h = (const float*)d_in[0];
    const float* edge_attr = (const float*)d_in[1];
    const int* batch = (const int*)d_in[2];
    const int* ei = (const int*)d_in[3];
    const float* w1 = (const float*)d_in[4];
    const float* b1 = (const float*)d_in[5];
    const float* we = (const float*)d_in[6];
    const float* be = (const float*)d_in[7];
    const float* eps = (const float*)d_in[8];
    const float* gnw = (const float*)d_in[9];
    const float* gnb = (const float*)d_in[10];
    const float* gnms = (const float*)d_in[11];
    float* out = (float*)d_out;

    cudaFuncSetAttribute(mma_gemm<false>, cudaFuncAttributeMaxDynamicSharedMemorySize, SMEM_SZ);
    cudaFuncSetAttribute(mma_gemm<true>, cudaFuncAttributeMaxDynamicSharedMemorySize, SMEM_SZ);

    const int NT_NODE = (NN + 127) / 128;   // 391
    const int NT_EDGE = (NE + 127) / 128;   // 4688
    const int GRID = 304;                   // 2 per SM (152 SMs)

    zero_agg_kernel<<<(NN * 32 + 255) / 256, 256>>>();                       // 1
    mma_gemm<false><<<GRID < NT_NODE ? GRID : NT_NODE, 256, SMEM_SZ>>>(
        node_h, w1, b1, nullptr, nullptr, NN, NT_NODE);                      // 2
    zero_stats_kernel<<<(GG * DD + 255) / 256, 256>>>();                     // 3
    mma_gemm<true><<<GRID, 256, SMEM_SZ>>>(edge_attr, we, be,
                                           ei, ei + NE, NE, NT_EDGE);        // 4
    stats3_kernel<<<(NN + 63) / 64, 256>>>(node_h, batch, eps);              // 5
    finalize_kernel<<<(GG * DD + 255) / 256, 256>>>(gnw, gnms);              // 6
    apply_kernel<<<(NN * 32 + 255) / 256, 256>>>(batch, gnb, out);           // 7
}